// round 1
// baseline (speedup 1.0000x reference)
#include <cuda_runtime.h>

#define B_TOT 65536
#define ALPHA 0.2f

typedef unsigned long long u64;

// wa1[f] = sum_o W[f][o]*a[o],  wa2[f] = sum_o W[f][o]*a[128+o]
__device__ float d_wa1[128];
__device__ float d_wa2[128];

__global__ void prep_kernel(const float* __restrict__ W, const float* __restrict__ a) {
    int f = threadIdx.x;
    float s1 = 0.f, s2 = 0.f;
#pragma unroll 8
    for (int o = 0; o < 128; o++) {
        float w = W[f * 128 + o];
        s1 = fmaf(w, a[o], s1);
        s2 = fmaf(w, a[128 + o], s2);
    }
    d_wa1[f] = s1;
    d_wa2[f] = s2;
}

__device__ __forceinline__ u64 fma2(u64 a, u64 b, u64 c) {
    u64 d;
    asm("fma.rn.f32x2 %0, %1, %2, %3;" : "=l"(d) : "l"(a), "l"(b), "l"(c));
    return d;
}
__device__ __forceinline__ float2 unpack2(u64 v) {
    float2 r;
    asm("mov.b64 {%0, %1}, %2;" : "=f"(r.x), "=f"(r.y) : "l"(v));
    return r;
}

// smem layout (floats):
//   [0, 16384)              W paired along K: element (k2, c) -> float2{W[2k2][c], W[2k2+1][c]} at offset k2*256 + c*2
//   [16384 + warp*1024, +1024)  per-warp g scratch [8 rows][128]
__launch_bounds__(256, 2)
__global__ void fused_gat_kernel(const float* __restrict__ h,
                                 const float* __restrict__ adj,
                                 const float* __restrict__ W,
                                 const float* __restrict__ a_node,
                                 float* __restrict__ out) {
    extern __shared__ float smem[];
    float* Wp = smem;
    int tid = threadIdx.x, lane = tid & 31, warp = tid >> 5;
    float* g_s = smem + 16384 + warp * 1024;

    // Build K-paired W in smem (one time per block)
    for (int idx = tid; idx < 8192; idx += 256) {
        int k2 = idx >> 7, c = idx & 127;
        float2 v = make_float2(W[(2 * k2) * 128 + c], W[(2 * k2 + 1) * 128 + c]);
        *(float2*)(Wp + idx * 2) = v;
    }
    __syncthreads();

    // per-lane fragments of the three dot vectors (cols lane*4 .. lane*4+3)
    float4 an = *(const float4*)(a_node + lane * 4);
    float4 v1 = *(const float4*)(d_wa1 + lane * 4);
    float4 v2 = *(const float4*)(d_wa2 + lane * 4);

    int warpsTotal = gridDim.x * 8;
    for (int b = blockIdx.x * 8 + warp; b < B_TOT; b += warpsTotal) {
        const float* hb = h + (size_t)b * 1024;
        float4 hv[8];
#pragma unroll
        for (int j = 0; j < 8; j++) hv[j] = *(const float4*)(hb + j * 128 + lane * 4);

        // ---- three 128-dim dots per row, warp-reduced so every lane has all 8 ----
        float en[8], s1[8], s2[8];
#pragma unroll
        for (int j = 0; j < 8; j++) {
            float pe = hv[j].x * an.x + hv[j].y * an.y + hv[j].z * an.z + hv[j].w * an.w;
            float p1 = hv[j].x * v1.x + hv[j].y * v1.y + hv[j].z * v1.z + hv[j].w * v1.w;
            float p2 = hv[j].x * v2.x + hv[j].y * v2.y + hv[j].z * v2.z + hv[j].w * v2.w;
#pragma unroll
            for (int off = 16; off; off >>= 1) {
                pe += __shfl_xor_sync(0xFFFFFFFFu, pe, off);
                p1 += __shfl_xor_sync(0xFFFFFFFFu, p1, off);
                p2 += __shfl_xor_sync(0xFFFFFFFFu, p2, off);
            }
            en[j] = pe; s1[j] = p1; s2[j] = p2;
        }

        // ---- node softmax over m (leaky relu, max-subtracted), residual scale ----
        float mx = -1e30f;
#pragma unroll
        for (int j = 0; j < 8; j++) {
            float v = en[j] > 0.f ? en[j] : ALPHA * en[j];
            en[j] = v;
            mx = fmaxf(mx, v);
        }
        float sum = 0.f;
#pragma unroll
        for (int j = 0; j < 8; j++) {
            float p = __expf(en[j] - mx);
            en[j] = p;
            sum += p;
        }
        float inv = 1.f / sum;
        float scale[8], Wh1[8], Wh2[8];
#pragma unroll
        for (int j = 0; j < 8; j++) {
            float sc = 1.f + en[j] * inv;
            scale[j] = sc;
            Wh1[j] = sc * s1[j];
            Wh2[j] = sc * s2[j];
        }

        // ---- edge attention rows + fold into g = att_s @ h ----
        const float* adjb = adj + (size_t)b * 64;
#pragma unroll
        for (int i = 0; i < 8; i++) {
            float4 A0 = *(const float4*)(adjb + i * 8);
            float4 A1 = *(const float4*)(adjb + i * 8 + 4);
            float adv[8] = {A0.x, A0.y, A0.z, A0.w, A1.x, A1.y, A1.z, A1.w};
            float ev[8];
            float m = -1e30f;
#pragma unroll
            for (int j = 0; j < 8; j++) {
                ev[j] = Wh1[j] + Wh2[i];
                if (adv[j] > 0.f) m = fmaxf(m, ev[j]);
            }
            float att[8];
            if (m == -1e30f) {
                // fully masked row: jax softmax of constant(-9e15) row -> uniform 1/8
#pragma unroll
                for (int j = 0; j < 8; j++) att[j] = 0.125f;
            } else {
                float s = 0.f;
#pragma unroll
                for (int j = 0; j < 8; j++) {
                    float p = (adv[j] > 0.f) ? __expf(ev[j] - m) : 0.f;
                    att[j] = p;
                    s += p;
                }
                float is = 1.f / s;
#pragma unroll
                for (int j = 0; j < 8; j++) att[j] *= is;
            }
            float4 g = make_float4(0.f, 0.f, 0.f, 0.f);
#pragma unroll
            for (int j = 0; j < 8; j++) {
                float c = att[j] * scale[j];
                g.x = fmaf(c, hv[j].x, g.x);
                g.y = fmaf(c, hv[j].y, g.y);
                g.z = fmaf(c, hv[j].z, g.z);
                g.w = fmaf(c, hv[j].w, g.w);
            }
            *(float4*)(g_s + i * 128 + lane * 4) = g;
        }
        __syncwarp();

        // ---- out = relu(g @ W), packed f32x2 with pairing along K ----
        // acc[i][c] is a u64 holding (even-k partial, odd-k partial)
        u64 acc[8][4];
#pragma unroll
        for (int i = 0; i < 8; i++) {
            acc[i][0] = 0ull; acc[i][1] = 0ull; acc[i][2] = 0ull; acc[i][3] = 0ull;
        }
#pragma unroll 8
        for (int k2 = 0; k2 < 64; k2++) {
            const float* wr = Wp + k2 * 256 + lane * 8;  // cols lane*4 .. lane*4+3, k pair k2
            ulonglong2 wA = *(const ulonglong2*)(wr);     // (c0, c1)
            ulonglong2 wB = *(const ulonglong2*)(wr + 4); // (c2, c3)
#pragma unroll
            for (int i = 0; i < 8; i++) {
                u64 gk = *(const u64*)(g_s + i * 128 + k2 * 2);  // uniform broadcast LDS.64
                acc[i][0] = fma2(gk, wA.x, acc[i][0]);
                acc[i][1] = fma2(gk, wA.y, acc[i][1]);
                acc[i][2] = fma2(gk, wB.x, acc[i][2]);
                acc[i][3] = fma2(gk, wB.y, acc[i][3]);
            }
        }

        float* ob = out + (size_t)b * 1024;
#pragma unroll
        for (int i = 0; i < 8; i++) {
            float2 c0 = unpack2(acc[i][0]), c1 = unpack2(acc[i][1]);
            float2 c2 = unpack2(acc[i][2]), c3 = unpack2(acc[i][3]);
            float4 o;
            o.x = fmaxf(c0.x + c0.y, 0.f);
            o.y = fmaxf(c1.x + c1.y, 0.f);
            o.z = fmaxf(c2.x + c2.y, 0.f);
            o.w = fmaxf(c3.x + c3.y, 0.f);
            *(float4*)(ob + i * 128 + lane * 4) = o;
        }
        __syncwarp();  // g_s reused next iteration
    }
}

extern "C" void kernel_launch(void* const* d_in, const int* in_sizes, int n_in,
                              void* d_out, int out_size) {
    const float* h      = (const float*)d_in[0];
    const float* adj    = (const float*)d_in[1];
    const float* W      = (const float*)d_in[2];
    const float* a      = (const float*)d_in[3];
    const float* a_node = (const float*)d_in[4];
    float* out = (float*)d_out;

    prep_kernel<<<1, 128>>>(W, a);

    const int smem_bytes = (16384 + 8 * 1024) * sizeof(float);  // 96 KB
    cudaFuncSetAttribute(fused_gat_kernel, cudaFuncAttributeMaxDynamicSharedMemorySize, smem_bytes);
    fused_gat_kernel<<<2048, 256, smem_bytes>>>(h, adj, W, a_node, out);
}

// round 4
// speedup vs baseline: 1.4711x; 1.4711x over previous
#include <cuda_runtime.h>
#include <cuda_fp16.h>

#define ALPHA 0.2f
#define B_TOT 65536

typedef unsigned int u32;

// ---- persistent prepped constants ----
__device__ float d_wa1[128];
__device__ float d_wa2[128];
__device__ __half d_Whi[16384];   // [n][k] = W[k][n], fp16 hi
__device__ __half d_Wlo[16384];   // residual lo

__global__ void prep_kernel(const float* __restrict__ W, const float* __restrict__ a) {
    int f = threadIdx.x;  // 0..127
    float s1 = 0.f, s2 = 0.f;
#pragma unroll 8
    for (int o = 0; o < 128; o++) {
        float w = W[f * 128 + o];
        s1 = fmaf(w, a[o], s1);
        s2 = fmaf(w, a[128 + o], s2);
    }
    d_wa1[f] = s1;
    d_wa2[f] = s2;
    for (int k = 0; k < 128; k++) {
        float w = W[k * 128 + f];            // row f of W^T = output column f
        __half hi = __float2half_rn(w);
        float lo = w - __half2float(hi);
        d_Whi[f * 128 + k] = hi;
        d_Wlo[f * 128 + k] = __float2half_rn(lo);
    }
}

// ---- smem layout (bytes). Rows padded to 272B (136 halves) for conflict-free ldmatrix ----
#define ROWB 272
#define OFF_WH 0                       // 128 rows * 272
#define OFF_WL 34816
#define OFF_A  69632                   // per-warp: hi 16*272, lo 16*272 (8704 B/warp)
#define SMEM_BYTES (69632 + 16 * 8704) // 208896

__device__ __forceinline__ u32 smem_u32(const void* p) {
    u32 a;
    asm("{ .reg .u64 t; cvta.to.shared.u64 t, %1; cvt.u32.u64 %0, t; }" : "=r"(a) : "l"(p));
    return a;
}
__device__ __forceinline__ void ldsm4(u32* r, u32 addr) {
    asm volatile("ldmatrix.sync.aligned.m8n8.x4.shared.b16 {%0,%1,%2,%3}, [%4];"
                 : "=r"(r[0]), "=r"(r[1]), "=r"(r[2]), "=r"(r[3]) : "r"(addr));
}
__device__ __forceinline__ void mma16816(float* c, const u32* a, u32 b0, u32 b1) {
    asm volatile("mma.sync.aligned.m16n8k16.row.col.f32.f16.f16.f32 "
                 "{%0,%1,%2,%3}, {%4,%5,%6,%7}, {%8,%9}, {%0,%1,%2,%3};"
                 : "+f"(c[0]), "+f"(c[1]), "+f"(c[2]), "+f"(c[3])
                 : "r"(a[0]), "r"(a[1]), "r"(a[2]), "r"(a[3]), "r"(b0), "r"(b1));
}

__global__ __launch_bounds__(512, 1) void fused_gat_hmma(
    const float* __restrict__ h, const float* __restrict__ adj,
    const float* __restrict__ a_node, float* __restrict__ out)
{
    extern __shared__ char sm[];
    const u32 smb = smem_u32(sm);
    int tid = threadIdx.x, lane = tid & 31, warp = tid >> 5;

    // ---- stage W^T hi/lo into padded smem (once per CTA) ----
    {
        const uint4* Wh = (const uint4*)d_Whi;   // 16B chunks: [row][c], c=0..15
        const uint4* Wl = (const uint4*)d_Wlo;
#pragma unroll
        for (int t = 0; t < 4; t++) {
            int idx = tid + t * 512;             // 2048 chunks
            int row = idx >> 4, c = idx & 15;
            *(uint4*)(sm + OFF_WH + row * ROWB + c * 16) = Wh[idx];
            *(uint4*)(sm + OFF_WL + row * ROWB + c * 16) = Wl[idx];
        }
    }
    __syncthreads();   // only CTA-wide sync; warps free-run afterwards

    float4 an = *(const float4*)(a_node + lane * 4);
    float4 v1 = *(const float4*)(d_wa1 + lane * 4);
    float4 v2 = *(const float4*)(d_wa2 + lane * 4);

    char* Ah = sm + OFF_A + warp * 8704;
    char* Al = Ah + 16 * ROWB;
    const int b0 = blockIdx.x * 32 + warp * 2;   // this warp's 2 batches

    // ================= scalar attention + fold (fp32, 2 batches) =================
#pragma unroll
    for (int bi = 0; bi < 2; bi++) {
        int b = b0 + bi;
        const float* hb = h + (size_t)b * 1024;
        float4 hv[8];
#pragma unroll
        for (int j = 0; j < 8; j++) hv[j] = *(const float4*)(hb + j * 128 + lane * 4);

        float en[8], s1[8], s2[8];
#pragma unroll
        for (int j = 0; j < 8; j++) {
            float pe = hv[j].x * an.x + hv[j].y * an.y + hv[j].z * an.z + hv[j].w * an.w;
            float p1 = hv[j].x * v1.x + hv[j].y * v1.y + hv[j].z * v1.z + hv[j].w * v1.w;
            float p2 = hv[j].x * v2.x + hv[j].y * v2.y + hv[j].z * v2.z + hv[j].w * v2.w;
#pragma unroll
            for (int off = 16; off; off >>= 1) {
                pe += __shfl_xor_sync(0xFFFFFFFFu, pe, off);
                p1 += __shfl_xor_sync(0xFFFFFFFFu, p1, off);
                p2 += __shfl_xor_sync(0xFFFFFFFFu, p2, off);
            }
            en[j] = pe; s1[j] = p1; s2[j] = p2;
        }

        float mx = -1e30f;
#pragma unroll
        for (int j = 0; j < 8; j++) {
            float v = en[j] > 0.f ? en[j] : ALPHA * en[j];
            en[j] = v; mx = fmaxf(mx, v);
        }
        float sum = 0.f;
#pragma unroll
        for (int j = 0; j < 8; j++) { float p = __expf(en[j] - mx); en[j] = p; sum += p; }
        float inv = 1.f / sum;
        float scale[8], Wh1[8], Wh2[8];
#pragma unroll
        for (int j = 0; j < 8; j++) {
            float sc = 1.f + en[j] * inv;
            scale[j] = sc; Wh1[j] = sc * s1[j]; Wh2[j] = sc * s2[j];
        }

        const float* adjb = adj + (size_t)b * 64;
#pragma unroll
        for (int i = 0; i < 8; i++) {
            float4 A0 = *(const float4*)(adjb + i * 8);
            float4 A1 = *(const float4*)(adjb + i * 8 + 4);
            float adv[8] = {A0.x, A0.y, A0.z, A0.w, A1.x, A1.y, A1.z, A1.w};
            float ev[8];
            float m = -1e30f;
#pragma unroll
            for (int j = 0; j < 8; j++) {
                ev[j] = Wh1[j] + Wh2[i];
                if (adv[j] > 0.f) m = fmaxf(m, ev[j]);
            }
            float att[8];
            if (m == -1e30f) {
#pragma unroll
                for (int j = 0; j < 8; j++) att[j] = 0.125f;   // jax softmax of constant row
            } else {
                float s = 0.f;
#pragma unroll
                for (int j = 0; j < 8; j++) {
                    float p = (adv[j] > 0.f) ? __expf(ev[j] - m) : 0.f;
                    att[j] = p; s += p;
                }
                float is = 1.f / s;
#pragma unroll
                for (int j = 0; j < 8; j++) att[j] *= is;
            }
            float4 g = make_float4(0.f, 0.f, 0.f, 0.f);
#pragma unroll
            for (int j = 0; j < 8; j++) {
                float c = att[j] * scale[j];
                g.x = fmaf(c, hv[j].x, g.x);
                g.y = fmaf(c, hv[j].y, g.y);
                g.z = fmaf(c, hv[j].z, g.z);
                g.w = fmaf(c, hv[j].w, g.w);
            }
            // fp16 hi/lo split -> per-warp A panel, row = bi*8+i, k cols lane*4..+3
            __half2 h01 = __floats2half2_rn(g.x, g.y);
            __half2 h23 = __floats2half2_rn(g.z, g.w);
            float2 f01 = __half22float2(h01);
            float2 f23 = __half22float2(h23);
            __half2 l01 = __floats2half2_rn(g.x - f01.x, g.y - f01.y);
            __half2 l23 = __floats2half2_rn(g.z - f23.x, g.w - f23.y);
            int row = bi * 8 + i;
            uint2 uh = make_uint2(*(u32*)&h01, *(u32*)&h23);
            uint2 ul = make_uint2(*(u32*)&l01, *(u32*)&l23);
            *(uint2*)(Ah + row * ROWB + lane * 8) = uh;
            *(uint2*)(Al + row * ROWB + lane * 8) = ul;
        }
    }
    __syncwarp();

    // ================= HMMA GEMM: out16x128 = relu(A @ W^T), 3 hi/lo passes =================
    float acc[16][4];
#pragma unroll
    for (int nt = 0; nt < 16; nt++) { acc[nt][0] = acc[nt][1] = acc[nt][2] = acc[nt][3] = 0.f; }

    const u32 ah_base = smb + (u32)(OFF_A + warp * 8704);
    const u32 al_base = ah_base + 16 * ROWB;
    // A frag addr: row = lane%16, +16B if lane>=16 (k high half)
    const u32 a_off = (u32)((lane & 15) * ROWB + (lane >> 4) * 16);
    // B frag addr: n = ntpair*16 + (lane>>4)*8 + (lane&7), +16B if (lane>>3)&1
    const u32 b_off = (u32)((((lane >> 4) << 3) + (lane & 7)) * ROWB + (((lane >> 3) & 1) << 4));

#pragma unroll
    for (int ks = 0; ks < 8; ks++) {          // K=128, 16 halves (32 B) per step
        u32 afh[4], afl[4];
        ldsm4(afh, ah_base + a_off + ks * 32);
        ldsm4(afl, al_base + a_off + ks * 32);
#pragma unroll
        for (int np = 0; np < 8; np++) {
            u32 bh[4], bl[4];
            u32 nb = smb + (u32)(np * 16 * ROWB) + b_off + ks * 32;
            ldsm4(bh, (u32)OFF_WH + nb);
            ldsm4(bl, (u32)OFF_WL + nb);
            mma16816(acc[2 * np],     afh, bh[0], bh[1]);
            mma16816(acc[2 * np],     afh, bl[0], bl[1]);
            mma16816(acc[2 * np],     afl, bh[0], bh[1]);
            mma16816(acc[2 * np + 1], afh, bh[2], bh[3]);
            mma16816(acc[2 * np + 1], afh, bl[2], bl[3]);
            mma16816(acc[2 * np + 1], afl, bh[2], bh[3]);
        }
    }

    // ---- epilogue: relu + store. c0,c1 -> row lane/4 (batch b0), c2,c3 -> row+8 (batch b0+1) ----
    {
        float* o0 = out + ((size_t)b0 * 8 + (lane >> 2)) * 128 + (lane & 3) * 2;
        float* o1 = o0 + 1024;
#pragma unroll
        for (int nt = 0; nt < 16; nt++) {
            float2 r0 = make_float2(fmaxf(acc[nt][0], 0.f), fmaxf(acc[nt][1], 0.f));
            float2 r1 = make_float2(fmaxf(acc[nt][2], 0.f), fmaxf(acc[nt][3], 0.f));
            *(float2*)(o0 + nt * 8) = r0;
            *(float2*)(o1 + nt * 8) = r1;
        }
    }
}

extern "C" void kernel_launch(void* const* d_in, const int* in_sizes, int n_in,
                              void* d_out, int out_size) {
    const float* h      = (const float*)d_in[0];
    const float* adj    = (const float*)d_in[1];
    const float* W      = (const float*)d_in[2];
    const float* a      = (const float*)d_in[3];
    const float* a_node = (const float*)d_in[4];
    float* out = (float*)d_out;

    prep_kernel<<<1, 128>>>(W, a);

    cudaFuncSetAttribute(fused_gat_hmma, cudaFuncAttributeMaxDynamicSharedMemorySize, SMEM_BYTES);
    fused_gat_hmma<<<B_TOT / 32, 512, SMEM_BYTES>>>(h, adj, a_node, out);
}

// round 5
// speedup vs baseline: 2.2339x; 1.5185x over previous
#include <cuda_runtime.h>
#include <cuda_fp16.h>

#define ALPHA 0.2f
#define B_TOT 65536

typedef unsigned int u32;

// ---- persistent prepped constants ----
__device__ float d_wa1[128];
__device__ __half d_Whi[16384];   // [n][k] = W[k][n], fp16 hi
__device__ __half d_Wlo[16384];   // residual lo

// Parallel prep: blocks 0..63 split W^T into hi/lo (256 elem each);
// blocks 64..191 compute wa1[f] with one warp each.
__global__ void prep_kernel(const float* __restrict__ W, const float* __restrict__ a) {
    int blk = blockIdx.x, tid = threadIdx.x;
    if (blk < 64) {
        int idx = blk * 256 + tid;            // (f,k): f=idx>>7, k=idx&127
        int f = idx >> 7, k = idx & 127;
        float w = W[k * 128 + f];
        __half hi = __float2half_rn(w);
        d_Whi[idx] = hi;
        d_Wlo[idx] = __float2half_rn(w - __half2float(hi));
    } else if (tid < 32) {
        int f = blk - 64;                     // 0..127
        float4 wv = *(const float4*)(W + f * 128 + tid * 4);
        float4 av = *(const float4*)(a + tid * 4);
        float p = wv.x * av.x + wv.y * av.y + wv.z * av.z + wv.w * av.w;
#pragma unroll
        for (int off = 16; off; off >>= 1) p += __shfl_xor_sync(0xFFFFFFFFu, p, off);
        if (tid == 0) d_wa1[f] = p;
    }
}

// ---- smem layout (bytes). Rows padded to 272B (136 halves) for conflict-free ldmatrix ----
#define ROWB 272
#define OFF_WH 0                       // 128 rows * 272
#define OFF_WL 34816
#define OFF_A  69632                   // per-warp: hi 16*272, lo 16*272 (8704 B/warp)
#define SMEM_BYTES (69632 + 16 * 8704) // 208896

__device__ __forceinline__ u32 smem_u32(const void* p) {
    u32 a;
    asm("{ .reg .u64 t; cvta.to.shared.u64 t, %1; cvt.u32.u64 %0, t; }" : "=r"(a) : "l"(p));
    return a;
}
__device__ __forceinline__ void ldsm4(u32* r, u32 addr) {
    asm volatile("ldmatrix.sync.aligned.m8n8.x4.shared.b16 {%0,%1,%2,%3}, [%4];"
                 : "=r"(r[0]), "=r"(r[1]), "=r"(r[2]), "=r"(r[3]) : "r"(addr));
}
__device__ __forceinline__ void mma16816(float* c, const u32* a, u32 b0, u32 b1) {
    asm volatile("mma.sync.aligned.m16n8k16.row.col.f32.f16.f16.f32 "
                 "{%0,%1,%2,%3}, {%4,%5,%6,%7}, {%8,%9}, {%0,%1,%2,%3};"
                 : "+f"(c[0]), "+f"(c[1]), "+f"(c[2]), "+f"(c[3])
                 : "r"(a[0]), "r"(a[1]), "r"(a[2]), "r"(a[3]), "r"(b0), "r"(b1));
}

__global__ __launch_bounds__(512, 1) void fused_gat_hmma(
    const float* __restrict__ h, const float* __restrict__ adj,
    const float* __restrict__ a_node, float* __restrict__ out)
{
    extern __shared__ char sm[];
    const u32 smb = smem_u32(sm);
    int tid = threadIdx.x, lane = tid & 31, warp = tid >> 5;

    // ---- stage W^T hi/lo into padded smem (once per CTA) ----
    {
        const uint4* Wh = (const uint4*)d_Whi;   // 16B chunks: [row][c], c=0..15
        const uint4* Wl = (const uint4*)d_Wlo;
#pragma unroll
        for (int t = 0; t < 4; t++) {
            int idx = tid + t * 512;             // 2048 chunks
            int row = idx >> 4, c = idx & 15;
            *(uint4*)(sm + OFF_WH + row * ROWB + c * 16) = Wh[idx];
            *(uint4*)(sm + OFF_WL + row * ROWB + c * 16) = Wl[idx];
        }
    }
    __syncthreads();   // only CTA-wide sync; warps free-run afterwards

    float4 an = *(const float4*)(a_node + lane * 4);
    float4 v1 = *(const float4*)(d_wa1 + lane * 4);

    char* Ah = sm + OFF_A + warp * 8704;
    char* Al = Ah + 16 * ROWB;
    const int b0 = blockIdx.x * 32 + warp * 2;   // this warp's 2 batches

    // ================= scalar attention + fold (fp32, 2 batches) =================
#pragma unroll
    for (int bi = 0; bi < 2; bi++) {
        int b = b0 + bi;
        const float* hb = h + (size_t)b * 1024;
        float4 hv[8];
#pragma unroll
        for (int j = 0; j < 8; j++) hv[j] = *(const float4*)(hb + j * 128 + lane * 4);

        // two 128-dim dots per row (e_n and h.wa1), warp-reduced to all lanes
        float en[8], s1[8];
#pragma unroll
        for (int j = 0; j < 8; j++) {
            float pe = hv[j].x * an.x + hv[j].y * an.y + hv[j].z * an.z + hv[j].w * an.w;
            float p1 = hv[j].x * v1.x + hv[j].y * v1.y + hv[j].z * v1.z + hv[j].w * v1.w;
#pragma unroll
            for (int off = 16; off; off >>= 1) {
                pe += __shfl_xor_sync(0xFFFFFFFFu, pe, off);
                p1 += __shfl_xor_sync(0xFFFFFFFFu, p1, off);
            }
            en[j] = pe; s1[j] = p1;
        }

        // node softmax (leaky, max-sub) + residual scale
        float mx = -1e30f;
#pragma unroll
        for (int j = 0; j < 8; j++) {
            float v = en[j] > 0.f ? en[j] : ALPHA * en[j];
            en[j] = v; mx = fmaxf(mx, v);
        }
        float sum = 0.f;
#pragma unroll
        for (int j = 0; j < 8; j++) { float p = __expf(en[j] - mx); en[j] = p; sum += p; }
        float inv = 1.f / sum;
        float scale[8], Wh1[8];
        float M = -1e30f;
#pragma unroll
        for (int j = 0; j < 8; j++) {
            float sc = 1.f + en[j] * inv;
            scale[j] = sc;
            Wh1[j] = sc * s1[j];
            M = fmaxf(M, Wh1[j]);
        }
        // Wh2[i] cancels in the row softmax: att[i][j] = masked-softmax_j(Wh1[j]).
        // One exp set per batch; per-row only a masked sum.
        float u[8], w[8];
#pragma unroll
        for (int j = 0; j < 8; j++) {
            u[j] = __expf(Wh1[j] - M);
            w[j] = u[j] * scale[j];
        }

        const float* adjb = adj + (size_t)b * 64;
#pragma unroll
        for (int i = 0; i < 8; i++) {
            float4 A0 = *(const float4*)(adjb + i * 8);
            float4 A1 = *(const float4*)(adjb + i * 8 + 4);
            float s = A0.x * u[0];
            s = fmaf(A0.y, u[1], s); s = fmaf(A0.z, u[2], s); s = fmaf(A0.w, u[3], s);
            s = fmaf(A1.x, u[4], s); s = fmaf(A1.y, u[5], s); s = fmaf(A1.z, u[6], s);
            s = fmaf(A1.w, u[7], s);
            float c[8], is;
            if (s != 0.f) {                       // warp-uniform branch
                is = __fdividef(1.f, s);
                c[0] = A0.x * w[0]; c[1] = A0.y * w[1]; c[2] = A0.z * w[2]; c[3] = A0.w * w[3];
                c[4] = A1.x * w[4]; c[5] = A1.y * w[5]; c[6] = A1.z * w[6]; c[7] = A1.w * w[7];
            } else {                              // fully-masked row: uniform 1/8
                is = 0.125f;
#pragma unroll
                for (int j = 0; j < 8; j++) c[j] = scale[j];
            }
            float4 g = make_float4(0.f, 0.f, 0.f, 0.f);
#pragma unroll
            for (int j = 0; j < 8; j++) {
                g.x = fmaf(c[j], hv[j].x, g.x);
                g.y = fmaf(c[j], hv[j].y, g.y);
                g.z = fmaf(c[j], hv[j].z, g.z);
                g.w = fmaf(c[j], hv[j].w, g.w);
            }
            g.x *= is; g.y *= is; g.z *= is; g.w *= is;

            // fp16 hi/lo split -> per-warp A panel, row = bi*8+i, k cols lane*4..+3
            __half2 h01 = __floats2half2_rn(g.x, g.y);
            __half2 h23 = __floats2half2_rn(g.z, g.w);
            float2 f01 = __half22float2(h01);
            float2 f23 = __half22float2(h23);
            __half2 l01 = __floats2half2_rn(g.x - f01.x, g.y - f01.y);
            __half2 l23 = __floats2half2_rn(g.z - f23.x, g.w - f23.y);
            int row = bi * 8 + i;
            uint2 uh = make_uint2(*(u32*)&h01, *(u32*)&h23);
            uint2 ul = make_uint2(*(u32*)&l01, *(u32*)&l23);
            *(uint2*)(Ah + row * ROWB + lane * 8) = uh;
            *(uint2*)(Al + row * ROWB + lane * 8) = ul;
        }
    }
    __syncwarp();

    // ================= HMMA GEMM: out16x128 = relu(A @ W^T), 3 hi/lo passes =================
    float acc[16][4];
#pragma unroll
    for (int nt = 0; nt < 16; nt++) { acc[nt][0] = acc[nt][1] = acc[nt][2] = acc[nt][3] = 0.f; }

    const u32 ah_base = smb + (u32)(OFF_A + warp * 8704);
    const u32 al_base = ah_base + 16 * ROWB;
    // A frag addr: row = lane%16, +16B if lane>=16 (k high half)
    const u32 a_off = (u32)((lane & 15) * ROWB + (lane >> 4) * 16);
    // B frag addr: n = ntpair*16 + (lane>>4)*8 + (lane&7), +16B if (lane>>3)&1
    const u32 b_off = (u32)((((lane >> 4) << 3) + (lane & 7)) * ROWB + (((lane >> 3) & 1) << 4));

#pragma unroll
    for (int ks = 0; ks < 8; ks++) {          // K=128, 16 halves (32 B) per step
        u32 afh[4], afl[4];
        ldsm4(afh, ah_base + a_off + ks * 32);
        ldsm4(afl, al_base + a_off + ks * 32);
#pragma unroll
        for (int np = 0; np < 8; np++) {
            u32 bh[4], bl[4];
            u32 nb = smb + (u32)(np * 16 * ROWB) + b_off + ks * 32;
            ldsm4(bh, (u32)OFF_WH + nb);
            ldsm4(bl, (u32)OFF_WL + nb);
            mma16816(acc[2 * np],     afh, bh[0], bh[1]);
            mma16816(acc[2 * np],     afh, bl[0], bl[1]);
            mma16816(acc[2 * np],     afl, bh[0], bh[1]);
            mma16816(acc[2 * np + 1], afh, bh[2], bh[3]);
            mma16816(acc[2 * np + 1], afh, bl[2], bl[3]);
            mma16816(acc[2 * np + 1], afl, bh[2], bh[3]);
        }
    }

    // ---- epilogue: relu + store. c0,c1 -> row lane/4 (batch b0), c2,c3 -> row+8 (batch b0+1) ----
    {
        float* o0 = out + ((size_t)b0 * 8 + (lane >> 2)) * 128 + (lane & 3) * 2;
        float* o1 = o0 + 1024;
#pragma unroll
        for (int nt = 0; nt < 16; nt++) {
            float2 r0 = make_float2(fmaxf(acc[nt][0], 0.f), fmaxf(acc[nt][1], 0.f));
            float2 r1 = make_float2(fmaxf(acc[nt][2], 0.f), fmaxf(acc[nt][3], 0.f));
            *(float2*)(o0 + nt * 8) = r0;
            *(float2*)(o1 + nt * 8) = r1;
        }
    }
}

extern "C" void kernel_launch(void* const* d_in, const int* in_sizes, int n_in,
                              void* d_out, int out_size) {
    const float* h      = (const float*)d_in[0];
    const float* adj    = (const float*)d_in[1];
    const float* W      = (const float*)d_in[2];
    const float* a      = (const float*)d_in[3];
    const float* a_node = (const float*)d_in[4];
    float* out = (float*)d_out;

    prep_kernel<<<192, 256>>>(W, a);

    cudaFuncSetAttribute(fused_gat_hmma, cudaFuncAttributeMaxDynamicSharedMemorySize, SMEM_BYTES);
    fused_gat_hmma<<<B_TOT / 32, 512, SMEM_BYTES>>>(h, adj, a_node, out);
}

// round 6
// speedup vs baseline: 2.2891x; 1.0247x over previous
#include <cuda_runtime.h>
#include <cuda_fp16.h>

#define ALPHA 0.2f
#define B_TOT 65536

typedef unsigned int u32;

// ---- persistent prepped constants ----
__device__ float d_wa1[128];
__device__ __half d_Whi[16384];   // [n][k] = W[k][n], fp16 hi
__device__ __half d_Wlo[16384];   // residual lo

// Parallel prep: blocks 0..63 split W^T into hi/lo; blocks 64..191 compute wa1.
__global__ void prep_kernel(const float* __restrict__ W, const float* __restrict__ a) {
    int blk = blockIdx.x, tid = threadIdx.x;
    if (blk < 64) {
        int idx = blk * 256 + tid;            // (f,k): f=idx>>7, k=idx&127
        int f = idx >> 7, k = idx & 127;
        float w = W[k * 128 + f];
        __half hi = __float2half_rn(w);
        d_Whi[idx] = hi;
        d_Wlo[idx] = __float2half_rn(w - __half2float(hi));
    } else if (tid < 32) {
        int f = blk - 64;                     // 0..127
        float4 wv = *(const float4*)(W + f * 128 + tid * 4);
        float4 av = *(const float4*)(a + tid * 4);
        float p = wv.x * av.x + wv.y * av.y + wv.z * av.z + wv.w * av.w;
#pragma unroll
        for (int off = 16; off; off >>= 1) p += __shfl_xor_sync(0xFFFFFFFFu, p, off);
        if (tid == 0) d_wa1[f] = p;
    }
}

// ---- smem layout (bytes). Rows padded to 272B (136 halves) for conflict-free ldmatrix ----
#define ROWB 272
#define OFF_WH 0                        // 128 rows * 272
#define OFF_WL 34816
#define OFF_A  69632                    // per-PAIR panel: 32 rows hi + 32 rows lo = 17408 B
#define PANELB 17408
#define SMEM_BYTES (69632 + 8 * PANELB) // 208896

__device__ __forceinline__ u32 smem_u32(const void* p) {
    u32 a;
    asm("{ .reg .u64 t; cvta.to.shared.u64 t, %1; cvt.u32.u64 %0, t; }" : "=r"(a) : "l"(p));
    return a;
}
__device__ __forceinline__ void ldsm4(u32* r, u32 addr) {
    asm volatile("ldmatrix.sync.aligned.m8n8.x4.shared.b16 {%0,%1,%2,%3}, [%4];"
                 : "=r"(r[0]), "=r"(r[1]), "=r"(r[2]), "=r"(r[3]) : "r"(addr));
}
__device__ __forceinline__ void mma16816(float* c, const u32* a, u32 b0, u32 b1) {
    asm volatile("mma.sync.aligned.m16n8k16.row.col.f32.f16.f16.f32 "
                 "{%0,%1,%2,%3}, {%4,%5,%6,%7}, {%8,%9}, {%0,%1,%2,%3};"
                 : "+f"(c[0]), "+f"(c[1]), "+f"(c[2]), "+f"(c[3])
                 : "r"(a[0]), "r"(a[1]), "r"(a[2]), "r"(a[3]), "r"(b0), "r"(b1));
}

__global__ __launch_bounds__(512, 1) void fused_gat_hmma(
    const float* __restrict__ h, const float* __restrict__ adj,
    const float* __restrict__ a_node, float* __restrict__ out)
{
    extern __shared__ char sm[];
    const u32 smb = smem_u32(sm);
    int tid = threadIdx.x, lane = tid & 31, warp = tid >> 5;
    int pair = warp >> 1, half = warp & 1;

    // ---- stage W^T hi/lo into padded smem (once per CTA) ----
    {
        const uint4* Wh = (const uint4*)d_Whi;   // 16B chunks: [row][c], c=0..15
        const uint4* Wl = (const uint4*)d_Wlo;
#pragma unroll
        for (int t = 0; t < 4; t++) {
            int idx = tid + t * 512;             // 2048 chunks
            int row = idx >> 4, c = idx & 15;
            *(uint4*)(sm + OFF_WH + row * ROWB + c * 16) = Wh[idx];
            *(uint4*)(sm + OFF_WL + row * ROWB + c * 16) = Wl[idx];
        }
    }
    __syncthreads();

    float4 an = *(const float4*)(a_node + lane * 4);
    float4 v1 = *(const float4*)(d_wa1 + lane * 4);

    char* Ah = sm + OFF_A + pair * PANELB;       // 32 rows (pair's 4 batches)
    char* Al = Ah + 32 * ROWB;
    const int bp = blockIdx.x * 32 + pair * 4;   // pair's first batch
    const int b0 = bp + half * 2;                // this warp's 2 batches

    // ================= scalar attention + fold (fp32, 2 batches) =================
#pragma unroll
    for (int bi = 0; bi < 2; bi++) {
        int b = b0 + bi;
        const float* hb = h + (size_t)b * 1024;
        float4 hv[8];
#pragma unroll
        for (int j = 0; j < 8; j++) hv[j] = *(const float4*)(hb + j * 128 + lane * 4);

        // two 128-dim dots per row (e_n and h.wa1), warp-reduced to all lanes
        float en[8], s1[8];
#pragma unroll
        for (int j = 0; j < 8; j++) {
            float pe = hv[j].x * an.x + hv[j].y * an.y + hv[j].z * an.z + hv[j].w * an.w;
            float p1 = hv[j].x * v1.x + hv[j].y * v1.y + hv[j].z * v1.z + hv[j].w * v1.w;
#pragma unroll
            for (int off = 16; off; off >>= 1) {
                pe += __shfl_xor_sync(0xFFFFFFFFu, pe, off);
                p1 += __shfl_xor_sync(0xFFFFFFFFu, p1, off);
            }
            en[j] = pe; s1[j] = p1;
        }

        // node softmax (leaky, max-sub) + residual scale
        float mx = -1e30f;
#pragma unroll
        for (int j = 0; j < 8; j++) {
            float v = en[j] > 0.f ? en[j] : ALPHA * en[j];
            en[j] = v; mx = fmaxf(mx, v);
        }
        float sum = 0.f;
#pragma unroll
        for (int j = 0; j < 8; j++) { float p = __expf(en[j] - mx); en[j] = p; sum += p; }
        float inv = 1.f / sum;
        float scale[8], Wh1[8];
        float M = -1e30f;
#pragma unroll
        for (int j = 0; j < 8; j++) {
            float sc = 1.f + en[j] * inv;
            scale[j] = sc;
            Wh1[j] = sc * s1[j];
            M = fmaxf(M, Wh1[j]);
        }
        // Wh2[i] cancels in the row softmax: att[i][j] = masked-softmax_j(Wh1[j]).
        float u[8], w[8];
#pragma unroll
        for (int j = 0; j < 8; j++) {
            u[j] = __expf(Wh1[j] - M);
            w[j] = u[j] * scale[j];
        }

        const float* adjb = adj + (size_t)b * 64;
#pragma unroll
        for (int i = 0; i < 8; i++) {
            float4 A0 = *(const float4*)(adjb + i * 8);
            float4 A1 = *(const float4*)(adjb + i * 8 + 4);
            float s = A0.x * u[0];
            s = fmaf(A0.y, u[1], s); s = fmaf(A0.z, u[2], s); s = fmaf(A0.w, u[3], s);
            s = fmaf(A1.x, u[4], s); s = fmaf(A1.y, u[5], s); s = fmaf(A1.z, u[6], s);
            s = fmaf(A1.w, u[7], s);
            float c[8], is;
            if (s != 0.f) {                       // warp-uniform branch
                is = __fdividef(1.f, s);
                c[0] = A0.x * w[0]; c[1] = A0.y * w[1]; c[2] = A0.z * w[2]; c[3] = A0.w * w[3];
                c[4] = A1.x * w[4]; c[5] = A1.y * w[5]; c[6] = A1.z * w[6]; c[7] = A1.w * w[7];
            } else {                              // fully-masked row: uniform 1/8
                is = 0.125f;
#pragma unroll
                for (int j = 0; j < 8; j++) c[j] = scale[j];
            }
            float4 g = make_float4(0.f, 0.f, 0.f, 0.f);
#pragma unroll
            for (int j = 0; j < 8; j++) {
                g.x = fmaf(c[j], hv[j].x, g.x);
                g.y = fmaf(c[j], hv[j].y, g.y);
                g.z = fmaf(c[j], hv[j].z, g.z);
                g.w = fmaf(c[j], hv[j].w, g.w);
            }
            g.x *= is; g.y *= is; g.z *= is; g.w *= is;

            // fp16 hi/lo split -> pair A panel, row = (half*2+bi)*8+i
            __half2 h01 = __floats2half2_rn(g.x, g.y);
            __half2 h23 = __floats2half2_rn(g.z, g.w);
            float2 f01 = __half22float2(h01);
            float2 f23 = __half22float2(h23);
            __half2 l01 = __floats2half2_rn(g.x - f01.x, g.y - f01.y);
            __half2 l23 = __floats2half2_rn(g.z - f23.x, g.w - f23.y);
            int row = (half * 2 + bi) * 8 + i;
            uint2 uh = make_uint2(*(u32*)&h01, *(u32*)&h23);
            uint2 ul = make_uint2(*(u32*)&l01, *(u32*)&l23);
            *(uint2*)(Ah + row * ROWB + lane * 8) = uh;
            *(uint2*)(Al + row * ROWB + lane * 8) = ul;
        }
    }
    // pair barrier: both warps' A rows visible before cross-read
    asm volatile("bar.sync %0, 64;" :: "r"(pair + 1) : "memory");

    // ====== HMMA GEMM: rows 0..31 (pair's 4 batches) x this warp's 64-col half ======
    float acc[16][4];   // [mt*8+nt][c]
#pragma unroll
    for (int t = 0; t < 16; t++) { acc[t][0] = acc[t][1] = acc[t][2] = acc[t][3] = 0.f; }

    const u32 ah_base = smb + (u32)(OFF_A + pair * PANELB);
    const u32 al_base = ah_base + 32 * ROWB;
    const u32 a_off = (u32)((lane & 15) * ROWB + (lane >> 4) * 16);
    // B row n = half*64 + np*16 + (lane>>4)*8 + (lane&7); +16B if (lane>>3)&1
    const u32 b_off = (u32)((half * 64 + ((lane >> 4) << 3) + (lane & 7)) * ROWB +
                            (((lane >> 3) & 1) << 4));

#pragma unroll
    for (int ks = 0; ks < 8; ks++) {
        u32 afh[2][4], afl[2][4];
#pragma unroll
        for (int mt = 0; mt < 2; mt++) {
            ldsm4(afh[mt], ah_base + a_off + mt * (16 * ROWB) + ks * 32);
            ldsm4(afl[mt], al_base + a_off + mt * (16 * ROWB) + ks * 32);
        }
#pragma unroll
        for (int np = 0; np < 4; np++) {
            u32 bh[4], bl[4];
            u32 nb = smb + (u32)(np * 16 * ROWB) + b_off + ks * 32;
            ldsm4(bh, (u32)OFF_WH + nb);
            ldsm4(bl, (u32)OFF_WL + nb);
#pragma unroll
            for (int mt = 0; mt < 2; mt++) {
                float* ac0 = acc[mt * 8 + 2 * np];
                float* ac1 = acc[mt * 8 + 2 * np + 1];
                mma16816(ac0, afh[mt], bh[0], bh[1]);
                mma16816(ac0, afh[mt], bl[0], bl[1]);
                mma16816(ac0, afl[mt], bh[0], bh[1]);
                mma16816(ac1, afh[mt], bh[2], bh[3]);
                mma16816(ac1, afh[mt], bl[2], bl[3]);
                mma16816(ac1, afl[mt], bh[2], bh[3]);
            }
        }
    }

    // ---- epilogue: relu + store ----
    // acc[mt*8+nt]: c0,c1 -> panel row mt*16+(lane>>2)  = batch bp+mt*2,   m-row lane>>2
    //               c2,c3 -> panel row mt*16+(lane>>2)+8 = batch bp+mt*2+1, m-row lane>>2
    // col = half*64 + nt*8 + (lane&3)*2
    {
#pragma unroll
        for (int mt = 0; mt < 2; mt++) {
            float* o0 = out + ((size_t)(bp + mt * 2) * 8 + (lane >> 2)) * 128 +
                        half * 64 + (lane & 3) * 2;
            float* o1 = o0 + 1024;
#pragma unroll
            for (int nt = 0; nt < 8; nt++) {
                float* ac = acc[mt * 8 + nt];
                float2 r0 = make_float2(fmaxf(ac[0], 0.f), fmaxf(ac[1], 0.f));
                float2 r1 = make_float2(fmaxf(ac[2], 0.f), fmaxf(ac[3], 0.f));
                *(float2*)(o0 + nt * 8) = r0;
                *(float2*)(o1 + nt * 8) = r1;
            }
        }
    }
}

extern "C" void kernel_launch(void* const* d_in, const int* in_sizes, int n_in,
                              void* d_out, int out_size) {
    const float* h      = (const float*)d_in[0];
    const float* adj    = (const float*)d_in[1];
    const float* W      = (const float*)d_in[2];
    const float* a      = (const float*)d_in[3];
    const float* a_node = (const float*)d_in[4];
    float* out = (float*)d_out;

    prep_kernel<<<192, 256>>>(W, a);

    cudaFuncSetAttribute(fused_gat_hmma, cudaFuncAttributeMaxDynamicSharedMemorySize, SMEM_BYTES);
    fused_gat_hmma<<<B_TOT / 32, 512, SMEM_BYTES>>>(h, adj, a_node, out);
}